// round 1
// baseline (speedup 1.0000x reference)
#include <cuda_runtime.h>

// Problem: N = 384 == batch == seq == dim.
// out[i] = softmax( (x2[i] @ (x1@W.T+b).T) / 1000 ) @ x2[i]   for i in 0..383
//
// Kernel 1: v1t[k][n] = sum_m x1[n][m]*W[k][m] + b[k]   (transposed Linear output)
// Kernel 2: fused per-batch attention, fp32, fully in smem/regs (no HBM intermediate).

constexpr int N  = 384;   // batch / seq / dim (all equal)
constexpr int D  = 384;
constexpr int BM = 32;    // query rows per block
constexpr int BK = 32;    // k-chunk / n-chunk
constexpr int TM = 4;     // micro-tile rows per thread
constexpr int TN = 12;    // micro-tile cols per thread
constexpr int THREADS = 256;   // 8 warps: (ty 0..7) x (tx 0..31); rows=8*4=32, cols=32*12=384
constexpr float SCALE_INV = 1.0f / 1000.0f;

// scratch for the shared K matrix (Linear output, transposed): 384*384*4 = 590 KB
__device__ float g_v1t[N * N];

// ---------------------------------------------------------------------------
// Kernel 1: v1t = (x1 @ W.T + b).T   i.e. v1t[k][n] = sum_m x1[n][m]*W[k][m] + b[k]
// ---------------------------------------------------------------------------
__global__ void linear_t_kernel(const float* __restrict__ x1,
                                const float* __restrict__ W,
                                const float* __restrict__ b) {
    __shared__ float sW[16][17];
    __shared__ float sX[16][17];
    const int tx = threadIdx.x;
    const int ty = threadIdx.y;
    const int k = blockIdx.y * 16 + ty;   // row of v1t (W row)
    const int n = blockIdx.x * 16 + tx;   // col of v1t (x1 row)

    float acc = 0.0f;
    for (int m0 = 0; m0 < N; m0 += 16) {
        sW[ty][tx] = W[k * N + m0 + tx];
        sX[ty][tx] = x1[(blockIdx.x * 16 + ty) * N + m0 + tx];
        __syncthreads();
#pragma unroll
        for (int mm = 0; mm < 16; ++mm)
            acc += sW[ty][mm] * sX[tx][mm];
        __syncthreads();
    }
    g_v1t[k * N + n] = acc + b[k];
}

// ---------------------------------------------------------------------------
// Kernel 2: fused attention per batch.
// Block handles (batch i, 32 query rows). Scores kept entirely in smem,
// Q kept transposed in smem, K/V chunks streamed as contiguous float4 copies.
// ---------------------------------------------------------------------------
__global__ void fused_attn_kernel(const float* __restrict__ x2,
                                  float* __restrict__ out) {
    extern __shared__ float smem[];
    float* sQt = smem;                          // [D][BM+1]  transposed Q (pad vs bank conflicts)
    float* sB  = sQt + D * (BM + 1);            // [BK][N]    K-chunk / V-chunk staging
    float* sS  = sB + BK * N;                   // [BM][N]    scores -> probabilities

    const int tid = threadIdx.x;
    const int tx = tid & 31;                    // lane
    const int ty = tid >> 5;                    // warp
    const int rbase = ty * TM;                  // 0..28
    const int cbase = tx * TN;                  // 0..372
    const int i  = blockIdx.y;                  // batch
    const int j0 = blockIdx.x * BM;             // query row base

    // ---- load Q = x2[i, j0:j0+32, :] transposed into sQt[k][j] ----
    const float* Q = x2 + ((size_t)i * N + j0) * (size_t)D;
    for (int u = tid; u < BM * D; u += THREADS) {
        const int j = u / D;
        const int k = u % D;
        sQt[k * (BM + 1) + j] = Q[u];           // global read coalesced over k
    }

    float acc[TM][TN];
#pragma unroll
    for (int r = 0; r < TM; ++r)
#pragma unroll
        for (int c = 0; c < TN; ++c) acc[r][c] = 0.0f;

    // ---- pass 1: S = Q @ v1t  (S[j][n] = sum_k Q[j][k] * v1t[k][n]) ----
    for (int k0 = 0; k0 < D; k0 += BK) {
        // contiguous copy: sB[kk][n] = v1t[k0+kk][n]
        const float4* src = reinterpret_cast<const float4*>(g_v1t + (size_t)k0 * N);
        float4* dst = reinterpret_cast<float4*>(sB);
        for (int u = tid; u < (BK * N) / 4; u += THREADS) dst[u] = src[u];
        __syncthreads();   // also covers the sQt fill on the first iteration
#pragma unroll
        for (int kk = 0; kk < BK; ++kk) {
            float a[TM];
#pragma unroll
            for (int r = 0; r < TM; ++r)
                a[r] = sQt[(k0 + kk) * (BM + 1) + rbase + r];   // warp-broadcast
            float bq[TN];
#pragma unroll
            for (int c = 0; c < TN; ++c)
                bq[c] = sB[kk * N + cbase + c];                  // vectorizable
#pragma unroll
            for (int r = 0; r < TM; ++r)
#pragma unroll
                for (int c = 0; c < TN; ++c)
                    acc[r][c] += a[r] * bq[c];
        }
        __syncthreads();
    }

    // ---- write scores to smem ----
#pragma unroll
    for (int r = 0; r < TM; ++r)
#pragma unroll
        for (int c = 0; c < TN; ++c)
            sS[(rbase + r) * N + cbase + c] = acc[r][c];
    __syncthreads();

    // ---- softmax over each row: warp ty handles rows rbase..rbase+3 ----
#pragma unroll
    for (int r = 0; r < TM; ++r) {
        const int row = rbase + r;
        float v[12];
        float m = -1e30f;
#pragma unroll
        for (int q = 0; q < 12; ++q) {
            v[q] = sS[row * N + tx + q * 32] * SCALE_INV;
            m = fmaxf(m, v[q]);
        }
#pragma unroll
        for (int o = 16; o > 0; o >>= 1)
            m = fmaxf(m, __shfl_xor_sync(0xffffffffu, m, o));
        float s = 0.0f;
#pragma unroll
        for (int q = 0; q < 12; ++q) { v[q] = __expf(v[q] - m); s += v[q]; }
#pragma unroll
        for (int o = 16; o > 0; o >>= 1)
            s += __shfl_xor_sync(0xffffffffu, s, o);
        const float inv = 1.0f / s;
#pragma unroll
        for (int q = 0; q < 12; ++q)
            sS[row * N + tx + q * 32] = v[q] * inv;
    }
    __syncthreads();

    // ---- pass 2: O = P @ V  (O[j][c] = sum_n P[j][n] * x2[i][n][c]) ----
#pragma unroll
    for (int r = 0; r < TM; ++r)
#pragma unroll
        for (int c = 0; c < TN; ++c) acc[r][c] = 0.0f;

    const float* V = x2 + (size_t)i * N * (size_t)D;
    for (int n0 = 0; n0 < N; n0 += BK) {
        // contiguous copy: sB[kk][c] = x2[i][n0+kk][c]
        const float4* src = reinterpret_cast<const float4*>(V + (size_t)n0 * D);
        float4* dst = reinterpret_cast<float4*>(sB);
        for (int u = tid; u < (BK * D) / 4; u += THREADS) dst[u] = src[u];
        __syncthreads();
#pragma unroll
        for (int kk = 0; kk < BK; ++kk) {
            float a[TM];
#pragma unroll
            for (int r = 0; r < TM; ++r)
                a[r] = sS[(rbase + r) * N + n0 + kk];            // warp-broadcast
            float bq[TN];
#pragma unroll
            for (int c = 0; c < TN; ++c)
                bq[c] = sB[kk * D + cbase + c];
#pragma unroll
            for (int r = 0; r < TM; ++r)
#pragma unroll
                for (int c = 0; c < TN; ++c)
                    acc[r][c] += a[r] * bq[c];
        }
        __syncthreads();
    }

    // ---- write output (float4, 16B-aligned: cbase*4 = 48*tx) ----
#pragma unroll
    for (int r = 0; r < TM; ++r) {
        float* orow = out + ((size_t)i * N + j0 + rbase + r) * (size_t)D + cbase;
#pragma unroll
        for (int c = 0; c < TN; c += 4) {
            float4 o4 = make_float4(acc[r][c], acc[r][c + 1], acc[r][c + 2], acc[r][c + 3]);
            *reinterpret_cast<float4*>(orow + c) = o4;
        }
    }
}

// ---------------------------------------------------------------------------
extern "C" void kernel_launch(void* const* d_in, const int* in_sizes, int n_in,
                              void* d_out, int out_size) {
    const float* x1 = (const float*)d_in[0];   // (384, 384)
    const float* x2 = (const float*)d_in[1];   // (384, 384, 384)
    const float* W  = (const float*)d_in[2];   // (384, 384)
    const float* b  = (const float*)d_in[3];   // (384,)
    float* out = (float*)d_out;                // (384, 384, 384)

    (void)in_sizes; (void)n_in; (void)out_size;

    // Kernel 1: v1t (tiny)
    {
        dim3 grid(N / 16, N / 16);
        dim3 block(16, 16);
        linear_t_kernel<<<grid, block>>>(x1, W, b);
    }

    // Kernel 2: fused attention
    {
        constexpr int SMEM_BYTES = (D * (BM + 1) + BK * N + BM * N) * (int)sizeof(float); // 148992
        cudaFuncSetAttribute(fused_attn_kernel,
                             cudaFuncAttributeMaxDynamicSharedMemorySize, SMEM_BYTES);
        dim3 grid(N / BM, N);   // (12 row-tiles, 384 batches)
        fused_attn_kernel<<<grid, THREADS, SMEM_BYTES>>>(x2, out);
    }
}

// round 2
// speedup vs baseline: 5.2824x; 5.2824x over previous
#include <cuda_runtime.h>
#include <cuda_bf16.h>
#include <cstdint>

// out[i] = softmax( (x2[i] @ v1^T) / 1000 ) @ x2[i],  v1 = x1@W.T + b,  N=384 everywhere.
// Scheme: P = 1/384 + delta  ->  out = colsum(x2[i])/384 + delta @ x2[i]
// GEMMs in bf16 mma.sync (m16n8k16), softmax + delta in fp32 registers.

constexpr int N = 384;
constexpr float SCALE_INV = 1.0f / 1000.0f;
constexpr float INV_N = 1.0f / 384.0f;

constexpr int QS = 392;   // sQ row stride (halves), pad 8 -> conflict-free ldmatrix
constexpr int BS = 24;    // sB1 row stride (halves): 16 data + 8 pad
constexpr int VS = 392;   // sV row stride (halves)

constexpr int SQ_BYTES = 128 * QS * 2;              // 100352
constexpr int SB_BYTES = 2 * N * BS * 2;            // 36864 (union with sV: 2*16*VS*2=25088)
constexpr int SROW_BYTES = 256 * 4;                 // 1024
constexpr int SMEM_TOTAL = SQ_BYTES + SB_BYTES + SROW_BYTES;  // 138240

__device__ __align__(16) __nv_bfloat16 g_v1[N * N];   // v1[n][k], bf16
__device__ float g_colsum[N * N];                     // colsum[i][c] = sum_n x2[i][n][c]

// ---------------------------------------------------------------------------
__device__ __forceinline__ uint32_t smem_u32(const void* p) {
    uint32_t a;
    asm("{ .reg .u64 t; cvta.to.shared.u64 t, %1; cvt.u32.u64 %0, t; }" : "=r"(a) : "l"(p));
    return a;
}
__device__ __forceinline__ void ldm4(uint32_t* r, uint32_t addr) {
    asm volatile("ldmatrix.sync.aligned.m8n8.x4.shared.b16 {%0,%1,%2,%3},[%4];"
                 : "=r"(r[0]), "=r"(r[1]), "=r"(r[2]), "=r"(r[3]) : "r"(addr));
}
__device__ __forceinline__ void ldm4t(uint32_t* r, uint32_t addr) {
    asm volatile("ldmatrix.sync.aligned.m8n8.x4.trans.shared.b16 {%0,%1,%2,%3},[%4];"
                 : "=r"(r[0]), "=r"(r[1]), "=r"(r[2]), "=r"(r[3]) : "r"(addr));
}
__device__ __forceinline__ void mma16816(float* d, const uint32_t* a, uint32_t b0, uint32_t b1) {
    asm volatile("mma.sync.aligned.m16n8k16.row.col.f32.bf16.bf16.f32 "
                 "{%0,%1,%2,%3},{%4,%5,%6,%7},{%8,%9},{%0,%1,%2,%3};"
                 : "+f"(d[0]), "+f"(d[1]), "+f"(d[2]), "+f"(d[3])
                 : "r"(a[0]), "r"(a[1]), "r"(a[2]), "r"(a[3]), "r"(b0), "r"(b1));
}
__device__ __forceinline__ uint32_t bf2_pack(float a, float b) {
    __nv_bfloat162 h = __floats2bfloat162_rn(a, b);
    return *reinterpret_cast<uint32_t*>(&h);
}

// ---------------------------------------------------------------------------
// v1[n][k] = sum_m x1[n][m]*W[k][m] + b[k]   (bf16 output)
// ---------------------------------------------------------------------------
__global__ void linear_kernel(const float* __restrict__ x1,
                              const float* __restrict__ W,
                              const float* __restrict__ b) {
    __shared__ float sW[16][17];
    __shared__ float sX[16][17];
    const int tx = threadIdx.x, ty = threadIdx.y;
    const int k = blockIdx.y * 16 + ty;
    const int n = blockIdx.x * 16 + tx;
    float acc = 0.0f;
    for (int m0 = 0; m0 < N; m0 += 16) {
        sW[ty][tx] = W[k * N + m0 + tx];
        sX[ty][tx] = x1[(blockIdx.x * 16 + ty) * N + m0 + tx];
        __syncthreads();
#pragma unroll
        for (int mm = 0; mm < 16; ++mm) acc += sW[ty][mm] * sX[tx][mm];
        __syncthreads();
    }
    g_v1[n * N + k] = __float2bfloat16(acc + b[k]);
}

// ---------------------------------------------------------------------------
// colsum[i][c] = sum_n x2[i][n][c]  (fp32)
// ---------------------------------------------------------------------------
__global__ void colsum_kernel(const float* __restrict__ x2) {
    const int i = blockIdx.x;
    const int c = threadIdx.x;
    const float* p = x2 + (size_t)i * N * N + c;
    float s = 0.0f;
#pragma unroll 8
    for (int n = 0; n < N; ++n) s += p[(size_t)n * N];
    g_colsum[i * N + c] = s;
}

// ---------------------------------------------------------------------------
// Fused attention: CTA = (128 q-rows, batch i). 8 warps = 4 (rows) x 2 (cols).
// ---------------------------------------------------------------------------
__global__ __launch_bounds__(256, 1)
void attn_kernel(const float* __restrict__ x2, float* __restrict__ out) {
    extern __shared__ char smem[];
    __nv_bfloat16* sQ = reinterpret_cast<__nv_bfloat16*>(smem);
    __nv_bfloat16* sB = reinterpret_cast<__nv_bfloat16*>(smem + SQ_BYTES);
    float* srow = reinterpret_cast<float*>(smem + SQ_BYTES + SB_BYTES);

    const int tid = threadIdx.x;
    const int lane = tid & 31;
    const int warp = tid >> 5;
    const int wr = warp & 3;      // row group: rows wr*32..+32
    const int wc = warp >> 2;     // col group: cols wc*192..+192
    const int i = blockIdx.y;
    const int j0 = blockIdx.x * 128;

    const uint32_t sQu = smem_u32(sQ);
    const uint32_t sBu = smem_u32(sB);

    // ldmatrix lane geometry
    const int rowA = (lane & 7) + ((lane >> 3) & 1) * 8;   // A tiles (non-trans)
    const int colA = (lane >> 4) * 8;
    const uint32_t aBase = sQu + ((wr * 32 + rowA) * QS + colA) * 2;

    const int rowB = (lane & 7) + ((lane >> 4) & 1) * 8;   // B1 tiles (non-trans)
    const int colB = ((lane >> 3) & 1) * 8;
    const uint32_t bBase1 = sBu + (rowB * BS + colB) * 2;

    const int rowV = (lane & 7) + ((lane >> 3) & 1) * 8;   // B2 tiles (trans)
    const int colV = ((lane >> 4) & 1) * 8;
    const uint32_t bBase2 = sBu + (rowV * VS + colV) * 2;

    // ---- stage Q (fp32 -> bf16) into sQ ----
    const float* Qg = x2 + ((size_t)i * N + j0) * N;
#pragma unroll
    for (int q = 0; q < 48; ++q) {
        int idx = tid + q * 256;            // 0..12287
        int row = idx / 96, c4 = idx % 96;
        float4 f = __ldg(reinterpret_cast<const float4*>(Qg + (size_t)row * N) + c4);
        uint2 u = make_uint2(bf2_pack(f.x, f.y), bf2_pack(f.z, f.w));
        *reinterpret_cast<uint2*>(sQ + row * QS + c4 * 4) = u;
    }

    float acc[2][24][4];
#pragma unroll
    for (int ma = 0; ma < 2; ++ma)
#pragma unroll
        for (int na = 0; na < 24; ++na)
#pragma unroll
            for (int r = 0; r < 4; ++r) acc[ma][na][r] = 0.0f;

    // =======================================================================
    // GEMM1: S = Q @ v1^T ; loop over k in chunks of 16, B chunk = v1[:, k16]
    // =======================================================================
    uint4 pre[3];
#pragma unroll
    for (int q = 0; q < 3; ++q) {                  // prefetch chunk 0
        int idx = tid + q * 256;                   // 0..767
        int row = idx >> 1, part = idx & 1;
        pre[q] = *reinterpret_cast<const uint4*>(g_v1 + row * N + part * 8);
    }

    for (int kc = 0; kc < 24; ++kc) {
        const int buf = kc & 1;
        __nv_bfloat16* sb = sB + buf * N * BS;
#pragma unroll
        for (int q = 0; q < 3; ++q) {
            int idx = tid + q * 256;
            int row = idx >> 1, part = idx & 1;
            *reinterpret_cast<uint4*>(sb + row * BS + part * 8) = pre[q];
        }
        __syncthreads();
        if (kc < 23) {
#pragma unroll
            for (int q = 0; q < 3; ++q) {
                int idx = tid + q * 256;
                int row = idx >> 1, part = idx & 1;
                pre[q] = *reinterpret_cast<const uint4*>(g_v1 + row * N + (kc + 1) * 16 + part * 8);
            }
        }
        uint32_t a[2][4];
#pragma unroll
        for (int ma = 0; ma < 2; ++ma)
            ldm4(a[ma], aBase + (ma * 16 * QS + kc * 16) * 2);
#pragma unroll
        for (int nbx = 0; nbx < 12; ++nbx) {
            uint32_t b[4];
            ldm4(b, bBase1 + (buf * N * BS + (wc * 192 + nbx * 16) * BS) * 2);
#pragma unroll
            for (int ma = 0; ma < 2; ++ma) {
                mma16816(acc[ma][2 * nbx], a[ma], b[0], b[1]);
                mma16816(acc[ma][2 * nbx + 1], a[ma], b[2], b[3]);
            }
        }
    }

    // =======================================================================
    // Softmax (no max-sub needed: |S/1000| < 0.1):  e = exp(z); delta = e/s - 1/N
    // =======================================================================
    float rs[2][2] = {{0.f, 0.f}, {0.f, 0.f}};
#pragma unroll
    for (int ma = 0; ma < 2; ++ma)
#pragma unroll
        for (int na = 0; na < 24; ++na) {
            float* d = acc[ma][na];
            d[0] = __expf(d[0] * SCALE_INV);
            d[1] = __expf(d[1] * SCALE_INV);
            d[2] = __expf(d[2] * SCALE_INV);
            d[3] = __expf(d[3] * SCALE_INV);
            rs[ma][0] += d[0] + d[1];
            rs[ma][1] += d[2] + d[3];
        }
#pragma unroll
    for (int ma = 0; ma < 2; ++ma)
#pragma unroll
        for (int h = 0; h < 2; ++h) {
            rs[ma][h] += __shfl_xor_sync(0xffffffffu, rs[ma][h], 1);
            rs[ma][h] += __shfl_xor_sync(0xffffffffu, rs[ma][h], 2);
        }
    if ((lane & 3) == 0) {
#pragma unroll
        for (int ma = 0; ma < 2; ++ma)
#pragma unroll
            for (int h = 0; h < 2; ++h)
                srow[wc * 128 + wr * 32 + ma * 16 + h * 8 + (lane >> 2)] = rs[ma][h];
    }
    __syncthreads();
    float invs[2][2];
#pragma unroll
    for (int ma = 0; ma < 2; ++ma)
#pragma unroll
        for (int h = 0; h < 2; ++h) {
            int r = wr * 32 + ma * 16 + h * 8 + (lane >> 2);
            invs[ma][h] = 1.0f / (srow[r] + srow[128 + r]);
        }

    // delta (bf16) overwrites sQ (Q is dead)
#pragma unroll
    for (int ma = 0; ma < 2; ++ma)
#pragma unroll
        for (int na = 0; na < 24; ++na) {
            int r = wr * 32 + ma * 16 + (lane >> 2);
            int c = wc * 192 + (na >> 1) * 16 + (na & 1) * 8 + (lane & 3) * 2;
            float* d = acc[ma][na];
            *reinterpret_cast<uint32_t*>(sQ + r * QS + c) =
                bf2_pack(d[0] * invs[ma][0] - INV_N, d[1] * invs[ma][0] - INV_N);
            *reinterpret_cast<uint32_t*>(sQ + (r + 8) * QS + c) =
                bf2_pack(d[2] * invs[ma][1] - INV_N, d[3] * invs[ma][1] - INV_N);
        }

    // =======================================================================
    // GEMM2: out_corr = delta @ V ; V chunks = x2[i][n16][:] fp32->bf16
    // =======================================================================
#pragma unroll
    for (int ma = 0; ma < 2; ++ma)
#pragma unroll
        for (int na = 0; na < 24; ++na)
#pragma unroll
            for (int r = 0; r < 4; ++r) acc[ma][na][r] = 0.0f;

    const float* Vg = x2 + (size_t)i * N * N;
    float4 vpre[6];
#pragma unroll
    for (int q = 0; q < 6; ++q) {                  // prefetch chunk 0
        int idx = tid + q * 256;                   // 0..1535
        int row = idx / 96, c4 = idx % 96;
        vpre[q] = __ldg(reinterpret_cast<const float4*>(Vg + (size_t)row * N) + c4);
    }

    for (int nc = 0; nc < 24; ++nc) {
        const int buf = nc & 1;
        __nv_bfloat16* sv = sB + buf * 16 * VS;
#pragma unroll
        for (int q = 0; q < 6; ++q) {
            int idx = tid + q * 256;
            int row = idx / 96, c4 = idx % 96;
            uint2 u = make_uint2(bf2_pack(vpre[q].x, vpre[q].y), bf2_pack(vpre[q].z, vpre[q].w));
            *reinterpret_cast<uint2*>(sv + row * VS + c4 * 4) = u;
        }
        __syncthreads();
        if (nc < 23) {
#pragma unroll
            for (int q = 0; q < 6; ++q) {
                int idx = tid + q * 256;
                int row = idx / 96, c4 = idx % 96;
                vpre[q] = __ldg(reinterpret_cast<const float4*>(
                              Vg + ((size_t)(nc + 1) * 16 + row) * N) + c4);
            }
        }
        uint32_t a[2][4];
#pragma unroll
        for (int ma = 0; ma < 2; ++ma)
            ldm4(a[ma], aBase + (ma * 16 * QS + nc * 16) * 2);
#pragma unroll
        for (int nbx = 0; nbx < 12; ++nbx) {
            uint32_t b[4];
            ldm4t(b, bBase2 + (buf * 16 * VS + wc * 192 + nbx * 16) * 2);
#pragma unroll
            for (int ma = 0; ma < 2; ++ma) {
                mma16816(acc[ma][2 * nbx], a[ma], b[0], b[1]);
                mma16816(acc[ma][2 * nbx + 1], a[ma], b[2], b[3]);
            }
        }
    }

    // ---- epilogue: out = acc + colsum/384 ----
    const float* cs = g_colsum + (size_t)i * N;
#pragma unroll
    for (int ma = 0; ma < 2; ++ma)
#pragma unroll
        for (int nbx = 0; nbx < 12; ++nbx)
#pragma unroll
            for (int ct = 0; ct < 2; ++ct) {
                int na = nbx * 2 + ct;
                int r = j0 + wr * 32 + ma * 16 + (lane >> 2);
                int c = wc * 192 + nbx * 16 + ct * 8 + (lane & 3) * 2;
                float cs0 = __ldg(cs + c) * INV_N;
                float cs1 = __ldg(cs + c + 1) * INV_N;
                float* d = acc[ma][na];
                float2 o0 = make_float2(d[0] + cs0, d[1] + cs1);
                float2 o1 = make_float2(d[2] + cs0, d[3] + cs1);
                *reinterpret_cast<float2*>(out + ((size_t)i * N + r) * N + c) = o0;
                *reinterpret_cast<float2*>(out + ((size_t)i * N + r + 8) * N + c) = o1;
            }
}

// ---------------------------------------------------------------------------
extern "C" void kernel_launch(void* const* d_in, const int* in_sizes, int n_in,
                              void* d_out, int out_size) {
    const float* x1 = (const float*)d_in[0];
    const float* x2 = (const float*)d_in[1];
    const float* W  = (const float*)d_in[2];
    const float* b  = (const float*)d_in[3];
    float* out = (float*)d_out;
    (void)in_sizes; (void)n_in; (void)out_size;

    {
        dim3 grid(N / 16, N / 16), block(16, 16);
        linear_kernel<<<grid, block>>>(x1, W, b);
    }
    colsum_kernel<<<N, N>>>(x2);
    {
        cudaFuncSetAttribute(attn_kernel, cudaFuncAttributeMaxDynamicSharedMemorySize, SMEM_TOTAL);
        dim3 grid(N / 128, N);
        attn_kernel<<<grid, 256, SMEM_TOTAL>>>(x2, out);
    }
}